// round 1
// baseline (speedup 1.0000x reference)
#include <cuda_runtime.h>

typedef unsigned long long ull;

#define N_ROWS   16384
#define DIN      128
#define DOUT     64
#define KDIM     16384
#define MIN_NORM 1e-15f
#define ART_CLAMP (1.0f - 1e-7f)
#define MAXNORM  (1.0f - 4e-3f)

#define BM   128
#define BK   32
#define AS_P 130   // padded pitch for transposed A tile (keeps 8B align, kills most conflicts)

// Intermediate tangent-space features (allocation-free scratch)
__device__ float g_tangent[N_ROWS * DOUT];

// ---------------------------------------------------------------------------
// helpers
// ---------------------------------------------------------------------------
__device__ __forceinline__ float reduce64(float v, float* sbuf, int tid) {
#pragma unroll
    for (int o = 16; o > 0; o >>= 1) v += __shfl_xor_sync(0xffffffffu, v, o);
    if ((tid & 31) == 0) sbuf[tid >> 5] = v;
    __syncthreads();
    float r = sbuf[0] + sbuf[1];
    __syncthreads();
    return r;
}

__device__ __forceinline__ ull ffma2(ull a, ull b, ull c) {
    ull d;
    asm("fma.rn.f32x2 %0, %1, %2, %3;" : "=l"(d) : "l"(a), "l"(b), "l"(c));
    return d;
}
__device__ __forceinline__ ull pack2(float x, float y) {
    ull r;
    asm("mov.b64 %0, {%1, %2};" : "=l"(r) : "f"(x), "f"(y));
    return r;
}
__device__ __forceinline__ float2 unpack2(ull v) {
    float2 f;
    asm("mov.b64 {%0, %1}, %2;" : "=f"(f.x), "=f"(f.y) : "l"(v));
    return f;
}

// ---------------------------------------------------------------------------
// Kernel A: hyperbolic transform -> tangent space
//   support      = mobius_matvec(W, x, c=1)
//   hyp_bias     = proj(expmap0(bias))
//   support      = proj(mobius_add(support, hyp_bias))
//   g_tangent    = logmap0(support)
// One block = 16 rows, 64 threads (thread j owns output col j).
// ---------------------------------------------------------------------------
__global__ __launch_bounds__(64) void transform_kernel(
    const float* __restrict__ X,
    const float* __restrict__ W,
    const float* __restrict__ bias)
{
    __shared__ float sW[DIN * DOUT];
    __shared__ float sx[DIN];
    __shared__ float sred[2];

    const int tid = threadIdx.x;

    // cache W in smem (32 KB)
    for (int i = tid; i < DIN * DOUT; i += 64) sW[i] = W[i];

    // ---- hyp_bias = proj(expmap0(bias)), computed generally (bias may be nonzero) ----
    float b  = bias[tid];
    float b2 = reduce64(b * b, sred, tid);
    float bn = fmaxf(sqrtf(b2), MIN_NORM);
    float e  = tanhf(bn) * b / bn;
    float e2 = reduce64(e * e, sred, tid);
    float en = fmaxf(sqrtf(e2), MIN_NORM);
    float h  = (en > MAXNORM) ? e * (MAXNORM / en) : e;
    float h2 = reduce64(h * h, sred, tid);

    const int row0 = blockIdx.x * 16;
    for (int rr = 0; rr < 16; ++rr) {
        const int row = row0 + rr;
        __syncthreads();
        sx[tid]      = X[row * DIN + tid];
        sx[tid + 64] = X[row * DIN + tid + 64];
        __syncthreads();

        float px = sx[tid] * sx[tid] + sx[tid + 64] * sx[tid + 64];
        float x2 = reduce64(px, sred, tid);

        float mx = 0.f;
#pragma unroll 8
        for (int k = 0; k < DIN; ++k) mx = fmaf(sx[k], sW[k * DOUT + tid], mx);

        float m2 = reduce64(mx * mx, sred, tid);
        float xn = fmaxf(sqrtf(x2), MIN_NORM);
        float mn = fmaxf(sqrtf(m2), MIN_NORM);

        // mobius_matvec (sqrt_c = 1)
        float artx = atanhf(fminf(xn, ART_CLAMP));
        float r    = tanhf(mn / xn * artx) * mx / mn;
        if (m2 == 0.f) r = 0.f;   // cond: all(mx == 0)

        // mobius_add(r, h), c = 1
        float r2  = reduce64(r * r, sred, tid);
        float rh  = reduce64(r * h, sred, tid);
        float al  = 1.f + 2.f * rh + h2;
        float num = al * r + (1.f - r2) * h;
        float den = fmaxf(1.f + 2.f * rh + r2 * h2, MIN_NORM);
        float p   = num / den;

        // proj
        float p2 = reduce64(p * p, sred, tid);
        float pn = fmaxf(sqrtf(p2), MIN_NORM);
        if (pn > MAXNORM) { p *= MAXNORM / pn; pn = MAXNORM; }

        // logmap0
        float t = atanhf(fminf(pn, ART_CLAMP)) / pn * p;
        g_tangent[row * DOUT + tid] = t;
    }
}

// ---------------------------------------------------------------------------
// Kernel B: out = relu(A @ g_tangent)   A:[16384,16384]  T:[16384,64]
// BM=128 rows/block, full 64 cols, BK=32. 256 threads, 8x4 microtile held as
// 16 packed f32x2 accumulators (fma.rn.f32x2 -> 2x fp32 FMA rate).
// Register-prefetch pipeline on global loads.
// ---------------------------------------------------------------------------
__global__ __launch_bounds__(256, 1) void spmm_kernel(
    const float* __restrict__ A,
    float* __restrict__ out)
{
    __shared__ float sA[BK * AS_P];   // transposed: sA[k][m]
    __shared__ float sT[BK * DOUT];   // sT[k][n]

    const int tid   = threadIdx.x;
    const int trow  = tid >> 4;       // 0..15
    const int tcol  = tid & 15;       // 0..15
    const int rbase = trow * 8;
    const int cbase = tcol * 4;

    // global load mapping
    const int aRow0 = tid >> 3;             // 0..31, +32*l
    const int aK0   = 4 * (tid & 7);        // k offset within tile
    const int tRow0 = tid >> 4;             // 0..15, +16*l
    const int tC0   = 4 * (tid & 15);

    const float* Ab = A + ((size_t)blockIdx.x * BM + aRow0) * KDIM + aK0;
    const float* Tb = g_tangent + (size_t)tRow0 * DOUT + tC0;

    float4 aR[4], tR[2];
#pragma unroll
    for (int l = 0; l < 4; ++l) aR[l] = *(const float4*)(Ab + (size_t)(32 * l) * KDIM);
#pragma unroll
    for (int l = 0; l < 2; ++l) tR[l] = *(const float4*)(Tb + (size_t)(16 * l) * DOUT);

    ull acc[4][4];
#pragma unroll
    for (int i = 0; i < 4; ++i)
#pragma unroll
        for (int j = 0; j < 4; ++j) acc[i][j] = 0ull;

    const int NT = KDIM / BK;
    for (int t = 0; t < NT; ++t) {
        // stage current tile regs -> smem (A transposed)
#pragma unroll
        for (int l = 0; l < 4; ++l) {
            const int m = aRow0 + 32 * l;
            sA[(aK0 + 0) * AS_P + m] = aR[l].x;
            sA[(aK0 + 1) * AS_P + m] = aR[l].y;
            sA[(aK0 + 2) * AS_P + m] = aR[l].z;
            sA[(aK0 + 3) * AS_P + m] = aR[l].w;
        }
#pragma unroll
        for (int l = 0; l < 2; ++l)
            *(float4*)&sT[(tRow0 + 16 * l) * DOUT + tC0] = tR[l];
        __syncthreads();

        // prefetch next tile into regs (latency hidden behind compute)
        if (t + 1 < NT) {
            const size_t k0 = (size_t)(t + 1) * BK;
#pragma unroll
            for (int l = 0; l < 4; ++l)
                aR[l] = *(const float4*)(Ab + (size_t)(32 * l) * KDIM + k0);
#pragma unroll
            for (int l = 0; l < 2; ++l)
                tR[l] = *(const float4*)(Tb + (k0 + 16 * l) * DOUT);
        }

        // compute: rows paired in f32x2 lanes
#pragma unroll
        for (int k = 0; k < BK; ++k) {
            const float* ap = &sA[k * AS_P + rbase];
            const ull a0 = *(const ull*)(ap + 0);
            const ull a1 = *(const ull*)(ap + 2);
            const ull a2 = *(const ull*)(ap + 4);
            const ull a3 = *(const ull*)(ap + 6);
            const float4 bv = *(const float4*)&sT[k * DOUT + cbase];
            const ull b0 = pack2(bv.x, bv.x);
            const ull b1 = pack2(bv.y, bv.y);
            const ull b2 = pack2(bv.z, bv.z);
            const ull b3 = pack2(bv.w, bv.w);
            acc[0][0] = ffma2(a0, b0, acc[0][0]);
            acc[0][1] = ffma2(a0, b1, acc[0][1]);
            acc[0][2] = ffma2(a0, b2, acc[0][2]);
            acc[0][3] = ffma2(a0, b3, acc[0][3]);
            acc[1][0] = ffma2(a1, b0, acc[1][0]);
            acc[1][1] = ffma2(a1, b1, acc[1][1]);
            acc[1][2] = ffma2(a1, b2, acc[1][2]);
            acc[1][3] = ffma2(a1, b3, acc[1][3]);
            acc[2][0] = ffma2(a2, b0, acc[2][0]);
            acc[2][1] = ffma2(a2, b1, acc[2][1]);
            acc[2][2] = ffma2(a2, b2, acc[2][2]);
            acc[2][3] = ffma2(a2, b3, acc[2][3]);
            acc[3][0] = ffma2(a3, b0, acc[3][0]);
            acc[3][1] = ffma2(a3, b1, acc[3][1]);
            acc[3][2] = ffma2(a3, b2, acc[3][2]);
            acc[3][3] = ffma2(a3, b3, acc[3][3]);
        }
        __syncthreads();
    }

    // epilogue: relu + store
    const int growBase = blockIdx.x * BM + rbase;
#pragma unroll
    for (int rp = 0; rp < 4; ++rp) {
#pragma unroll
        for (int c = 0; c < 4; ++c) {
            const float2 v = unpack2(acc[rp][c]);
            out[(size_t)(growBase + 2 * rp + 0) * DOUT + cbase + c] = fmaxf(v.x, 0.f);
            out[(size_t)(growBase + 2 * rp + 1) * DOUT + cbase + c] = fmaxf(v.y, 0.f);
        }
    }
}

// ---------------------------------------------------------------------------
extern "C" void kernel_launch(void* const* d_in, const int* in_sizes, int n_in,
                              void* d_out, int out_size)
{
    const float* adj  = (const float*)d_in[0];   // [16384, 16384]
    const float* x    = (const float*)d_in[1];   // [16384, 128]
    const float* w    = (const float*)d_in[2];   // [128, 64]
    const float* bias = (const float*)d_in[3];   // [64]
    float* out = (float*)d_out;                  // [16384, 64]

    transform_kernel<<<N_ROWS / 16, 64>>>(x, w, bias);
    spmm_kernel<<<N_ROWS / BM, 256>>>(adj, out);
}

// round 3
// speedup vs baseline: 1.1296x; 1.1296x over previous
#include <cuda_runtime.h>
#include <cuda_bf16.h>
#include <cstdint>

#define N_ROWS   16384
#define DIN      128
#define DOUT     64
#define KDIM     16384
#define MIN_NORM 1e-15f
#define ART_CLAMP (1.0f - 1e-7f)
#define MAXNORM  (1.0f - 4e-3f)

#define TK     64            // k per chunk
#define NCH    (KDIM / TK)   // 256 chunks
#define BPITCH 144           // B smem row pitch bytes (64 bf16 = 128B + 16B pad, conflict-free ldmatrix)
#define BTILE  (64 * BPITCH) // 9216 B per (hi|lo) tile

// Pre-split, pre-transposed tangent matrix: [DOUT][KDIM] K-major bf16
__device__ __nv_bfloat16 g_Bhi[DOUT * KDIM];
__device__ __nv_bfloat16 g_Blo[DOUT * KDIM];

// ---------------------------------------------------------------------------
// helpers
// ---------------------------------------------------------------------------
__device__ __forceinline__ uint32_t smem_u32(const void* p) {
    uint32_t a;
    asm("{ .reg .u64 t; cvta.to.shared.u64 t, %1; cvt.u32.u64 %0, t; }" : "=r"(a) : "l"(p));
    return a;
}
__device__ __forceinline__ uint32_t cvt_bf16x2(float lo, float hi) {
    uint32_t r;
    asm("cvt.rn.bf16x2.f32 %0, %1, %2;" : "=r"(r) : "f"(hi), "f"(lo));
    return r;
}
__device__ __forceinline__ void cp_async16(uint32_t dst, const void* src) {
    asm volatile(
        "{ .reg .u64 gp; cvta.to.global.u64 gp, %1;"
        " cp.async.cg.shared.global [%0], [gp], 16; }"
        :: "r"(dst), "l"(src) : "memory");
}
#define CP_COMMIT()  asm volatile("cp.async.commit_group;" ::: "memory")
#define CP_WAIT1()   asm volatile("cp.async.wait_group 1;" ::: "memory")
#define CP_WAIT0()   asm volatile("cp.async.wait_group 0;" ::: "memory")

__device__ __forceinline__ void ldsm4(uint32_t addr, uint32_t& r0, uint32_t& r1,
                                      uint32_t& r2, uint32_t& r3) {
    asm volatile("ldmatrix.sync.aligned.m8n8.x4.shared.b16 {%0,%1,%2,%3}, [%4];"
                 : "=r"(r0), "=r"(r1), "=r"(r2), "=r"(r3) : "r"(addr));
}
__device__ __forceinline__ void mma_bf16(float* c, const uint32_t* a,
                                         uint32_t b0, uint32_t b1) {
    asm volatile(
        "mma.sync.aligned.m16n8k16.row.col.f32.bf16.bf16.f32 "
        "{%0,%1,%2,%3}, {%4,%5,%6,%7}, {%8,%9}, {%0,%1,%2,%3};"
        : "+f"(c[0]), "+f"(c[1]), "+f"(c[2]), "+f"(c[3])
        : "r"(a[0]), "r"(a[1]), "r"(a[2]), "r"(a[3]), "r"(b0), "r"(b1));
}

// ---------------------------------------------------------------------------
// Kernel A: hyperbolic transform -> tangent, split to bf16 hi/lo, transposed
// to K-major [DOUT][KDIM] for the GEMM's B operand.
// ---------------------------------------------------------------------------
__device__ __forceinline__ float reduce64(float v, float* sbuf, int tid) {
#pragma unroll
    for (int o = 16; o > 0; o >>= 1) v += __shfl_xor_sync(0xffffffffu, v, o);
    if ((tid & 31) == 0) sbuf[tid >> 5] = v;
    __syncthreads();
    float r = sbuf[0] + sbuf[1];
    __syncthreads();
    return r;
}

__global__ __launch_bounds__(64) void transform_kernel(
    const float* __restrict__ X,
    const float* __restrict__ W,
    const float* __restrict__ bias)
{
    __shared__ float sW[DIN * DOUT];
    __shared__ float sx[DIN];
    __shared__ float sred[2];

    const int tid = threadIdx.x;

    for (int i = tid; i < DIN * DOUT; i += 64) sW[i] = W[i];

    // hyp_bias = proj(expmap0(bias))
    float b  = bias[tid];
    float b2 = reduce64(b * b, sred, tid);
    float bn = fmaxf(sqrtf(b2), MIN_NORM);
    float e  = tanhf(bn) * b / bn;
    float e2 = reduce64(e * e, sred, tid);
    float en = fmaxf(sqrtf(e2), MIN_NORM);
    float h  = (en > MAXNORM) ? e * (MAXNORM / en) : e;
    float h2 = reduce64(h * h, sred, tid);

    const int row0 = blockIdx.x * 16;
    for (int rr = 0; rr < 16; ++rr) {
        const int row = row0 + rr;
        __syncthreads();
        sx[tid]      = X[row * DIN + tid];
        sx[tid + 64] = X[row * DIN + tid + 64];
        __syncthreads();

        float px = sx[tid] * sx[tid] + sx[tid + 64] * sx[tid + 64];
        float x2 = reduce64(px, sred, tid);

        float mx = 0.f;
#pragma unroll 8
        for (int k = 0; k < DIN; ++k) mx = fmaf(sx[k], sW[k * DOUT + tid], mx);

        float m2 = reduce64(mx * mx, sred, tid);
        float xn = fmaxf(sqrtf(x2), MIN_NORM);
        float mn = fmaxf(sqrtf(m2), MIN_NORM);

        float artx = atanhf(fminf(xn, ART_CLAMP));
        float r    = tanhf(mn / xn * artx) * mx / mn;
        if (m2 == 0.f) r = 0.f;

        float r2  = reduce64(r * r, sred, tid);
        float rh  = reduce64(r * h, sred, tid);
        float al  = 1.f + 2.f * rh + h2;
        float num = al * r + (1.f - r2) * h;
        float den = fmaxf(1.f + 2.f * rh + r2 * h2, MIN_NORM);
        float p   = num / den;

        float p2 = reduce64(p * p, sred, tid);
        float pn = fmaxf(sqrtf(p2), MIN_NORM);
        if (pn > MAXNORM) { p *= MAXNORM / pn; pn = MAXNORM; }

        float t = atanhf(fminf(pn, ART_CLAMP)) / pn * p;

        __nv_bfloat16 th = __float2bfloat16(t);
        float tl = t - __bfloat162float(th);
        g_Bhi[(size_t)tid * KDIM + row] = th;
        g_Blo[(size_t)tid * KDIM + row] = __float2bfloat16(tl);
    }
}

// ---------------------------------------------------------------------------
// Kernel B: out = relu(A @ T) via mma.sync bf16-split (ah*bh + ah*bl + al*bh).
// 128 CTAs x 256 thr. M-tile 128 (8 warps x 16 rows), N = 64, K-chunk 64.
// A: direct LDG in fragment-ownership pattern, fp32->bf16 hi/lo in registers.
// B: cp.async staged (double-buffered), ldmatrix.x4 with 144B pitch.
// ---------------------------------------------------------------------------
struct APre { float2 v[16]; };   // [kf*4 + j]: j= {(g,c0),(g,c0+8),(g+8,c0),(g+8,c0+8)}

__device__ __forceinline__ void ldA(APre& p, const float* pa0, const float* pa8, int kb) {
#pragma unroll
    for (int kf = 0; kf < 4; ++kf) {
        p.v[kf * 4 + 0] = *(const float2*)(pa0 + kb + kf * 16);
        p.v[kf * 4 + 1] = *(const float2*)(pa0 + kb + kf * 16 + 8);
        p.v[kf * 4 + 2] = *(const float2*)(pa8 + kb + kf * 16);
        p.v[kf * 4 + 3] = *(const float2*)(pa8 + kb + kf * 16 + 8);
    }
}

// convert APre into mma-ordered fragments: a0=(g,c0) a1=(g+8,c0) a2=(g,c0+8) a3=(g+8,c0+8)
__device__ __forceinline__ void cvtA(const APre& p, uint32_t* ah, uint32_t* al) {
    const int map[4] = {0, 2, 1, 3};
#pragma unroll
    for (int kf = 0; kf < 4; ++kf) {
#pragma unroll
        for (int j = 0; j < 4; ++j) {
            float2 v = p.v[kf * 4 + map[j]];
            uint32_t h = cvt_bf16x2(v.x, v.y);
            float lx = v.x - __uint_as_float(h << 16);
            float ly = v.y - __uint_as_float(h & 0xFFFF0000u);
            ah[kf * 4 + j] = h;
            al[kf * 4 + j] = cvt_bf16x2(lx, ly);
        }
    }
}

__global__ __launch_bounds__(256, 1) void gemm_kernel(
    const float* __restrict__ A,
    float* __restrict__ out)
{
    __shared__ __align__(128) char sB[2][2][BTILE];   // [buf][hi/lo][64 rows * 144B]

    const int tid  = threadIdx.x;
    const int w    = tid >> 5;
    const int lane = tid & 31;
    const int g    = lane >> 2;
    const int t4   = lane & 3;
    const int m0   = blockIdx.x * 128;

    // A pointers: rows m0 + w*16 + g (+8), fragment cols t4*2 (+1)
    const float* pa0 = A + (size_t)(m0 + w * 16 + g) * KDIM + 2 * t4;
    const float* pa8 = pa0 + (size_t)8 * KDIM;

    // B cp.async mapping: two 16B chunks per thread per (hi|lo)
    const int n0 = tid >> 3, q0 = tid & 7;                 // idx = tid
    const int n1 = (tid + 256) >> 3, q1 = tid & 7;         // idx = tid + 256
    const uint32_t sb00 = smem_u32(&sB[0][0][0]);
    const uint32_t dOff0 = (uint32_t)(n0 * BPITCH + q0 * 16);
    const uint32_t dOff1 = (uint32_t)(n1 * BPITCH + q1 * 16);

    // ldmatrix lane offset: row (lane&7) of matrix (lane>>3)
    const uint32_t lmOff = (uint32_t)((lane & 7) * BPITCH + (lane >> 3) * 16);

    float acc[8][4];
#pragma unroll
    for (int i = 0; i < 8; ++i)
#pragma unroll
        for (int j = 0; j < 4; ++j) acc[i][j] = 0.f;

    // issue B chunk 0
    {
        const int kb = 0;
        cp_async16(sb00 + dOff0,         &g_Bhi[(size_t)n0 * KDIM + kb + q0 * 8]);
        cp_async16(sb00 + dOff1,         &g_Bhi[(size_t)n1 * KDIM + kb + q1 * 8]);
        cp_async16(sb00 + BTILE + dOff0, &g_Blo[(size_t)n0 * KDIM + kb + q0 * 8]);
        cp_async16(sb00 + BTILE + dOff1, &g_Blo[(size_t)n1 * KDIM + kb + q1 * 8]);
        CP_COMMIT();
    }

    APre pre0, pre1;
    ldA(pre0, pa0, pa8, 0);

    uint32_t ah[16], al[16];

    for (int i = 0; i < NCH; ++i) {
        const int buf = i & 1;
        APre& cur = (i & 1) ? pre1 : pre0;
        APre& nxt = (i & 1) ? pre0 : pre1;

        // issue B chunk i+1 into other buffer
        if (i + 1 < NCH) {
            const int kb = (i + 1) * TK;
            const uint32_t db = sb00 + (uint32_t)((buf ^ 1) * 2 * BTILE);
            cp_async16(db + dOff0,         &g_Bhi[(size_t)n0 * KDIM + kb + q0 * 8]);
            cp_async16(db + dOff1,         &g_Bhi[(size_t)n1 * KDIM + kb + q1 * 8]);
            cp_async16(db + BTILE + dOff0, &g_Blo[(size_t)n0 * KDIM + kb + q0 * 8]);
            cp_async16(db + BTILE + dOff1, &g_Blo[(size_t)n1 * KDIM + kb + q1 * 8]);
            CP_COMMIT();
            // prefetch A chunk i+1 into the other register set
            ldA(nxt, pa0, pa8, (i + 1) * TK);
        }

        // convert current A chunk to fragments (overlaps LDG latency of nxt)
        cvtA(cur, ah, al);

        // wait for B chunk i
        if (i + 1 < NCH) { CP_WAIT1(); } else { CP_WAIT0(); }
        __syncthreads();

        const uint32_t bhBase = sb00 + (uint32_t)(buf * 2 * BTILE) + lmOff;
        const uint32_t blBase = bhBase + BTILE;

#pragma unroll
        for (int p = 0; p < 2; ++p) {
#pragma unroll
            for (int nt = 0; nt < 8; ++nt) {
                uint32_t bh0, bh1, bh2, bh3, bl0, bl1, bl2, bl3;
                const uint32_t off = (uint32_t)(nt * 8 * BPITCH + p * 64);
                ldsm4(bhBase + off, bh0, bh1, bh2, bh3);
                ldsm4(blBase + off, bl0, bl1, bl2, bl3);
                const uint32_t* ah0 = ah + (2 * p) * 4;
                const uint32_t* al0 = al + (2 * p) * 4;
                const uint32_t* ah1 = ah + (2 * p + 1) * 4;
                const uint32_t* al1 = al + (2 * p + 1) * 4;
                mma_bf16(acc[nt], ah0, bh0, bh1);
                mma_bf16(acc[nt], al0, bh0, bh1);
                mma_bf16(acc[nt], ah0, bl0, bl1);
                mma_bf16(acc[nt], ah1, bh2, bh3);
                mma_bf16(acc[nt], al1, bh2, bh3);
                mma_bf16(acc[nt], ah1, bl2, bl3);
            }
        }
        __syncthreads();
    }

    // epilogue: relu + store. c0,c1=(row g, col nt*8+t4*2,+1); c2,c3=(row g+8)
    const int rowTop = m0 + w * 16 + g;
#pragma unroll
    for (int nt = 0; nt < 8; ++nt) {
        const int col = nt * 8 + t4 * 2;
        float2 v0 = make_float2(fmaxf(acc[nt][0], 0.f), fmaxf(acc[nt][1], 0.f));
        float2 v1 = make_float2(fmaxf(acc[nt][2], 0.f), fmaxf(acc[nt][3], 0.f));
        *(float2*)(out + (size_t)rowTop * DOUT + col)       = v0;
        *(float2*)(out + (size_t)(rowTop + 8) * DOUT + col) = v1;
    }
}

// ---------------------------------------------------------------------------
extern "C" void kernel_launch(void* const* d_in, const int* in_sizes, int n_in,
                              void* d_out, int out_size)
{
    const float* adj  = (const float*)d_in[0];   // [16384, 16384]
    const float* x    = (const float*)d_in[1];   // [16384, 128]
    const float* w    = (const float*)d_in[2];   // [128, 64]
    const float* bias = (const float*)d_in[3];   // [64]
    float* out = (float*)d_out;                  // [16384, 64]

    transform_kernel<<<N_ROWS / 16, 64>>>(x, w, bias);
    gemm_kernel<<<N_ROWS / 128, 256>>>(adj, out);
}

// round 4
// speedup vs baseline: 1.9752x; 1.7486x over previous
#include <cuda_runtime.h>
#include <cuda_bf16.h>
#include <cstdint>

#define N_ROWS   16384
#define DIN      128
#define DOUT     64
#define KDIM     16384
#define MIN_NORM 1e-15f
#define ART_CLAMP (1.0f - 1e-7f)
#define MAXNORM  (1.0f - 4e-3f)

#define TK      64            // k per chunk
#define NCH     (KDIM / TK)   // 256 chunks
#define BPITCH  144           // B smem row pitch (128B data + 16B pad, conflict-free ldmatrix)
#define BTILE   (64 * BPITCH) // 9216 B per (hi|lo) tile
#define BSTAGES 3
#define SMEM_B_BYTES (BSTAGES * 2 * BTILE)   // 55296

// Pre-split, pre-transposed tangent matrix: [DOUT][KDIM] K-major bf16
__device__ __nv_bfloat16 g_Bhi[DOUT * KDIM];
__device__ __nv_bfloat16 g_Blo[DOUT * KDIM];

// ---------------------------------------------------------------------------
// helpers
// ---------------------------------------------------------------------------
__device__ __forceinline__ uint32_t smem_u32(const void* p) {
    uint32_t a;
    asm("{ .reg .u64 t; cvta.to.shared.u64 t, %1; cvt.u32.u64 %0, t; }" : "=r"(a) : "l"(p));
    return a;
}
__device__ __forceinline__ uint32_t cvt_bf16x2(float lo, float hi) {
    uint32_t r;
    asm("cvt.rn.bf16x2.f32 %0, %1, %2;" : "=r"(r) : "f"(hi), "f"(lo));
    return r;
}
__device__ __forceinline__ void cp_async16(uint32_t dst, const void* src) {
    asm volatile(
        "{ .reg .u64 gp; cvta.to.global.u64 gp, %1;"
        " cp.async.cg.shared.global [%0], [gp], 16; }"
        :: "r"(dst), "l"(src) : "memory");
}
#define CP_COMMIT()  asm volatile("cp.async.commit_group;" ::: "memory")
#define CP_WAIT1()   asm volatile("cp.async.wait_group 1;" ::: "memory")
#define CP_WAIT0()   asm volatile("cp.async.wait_group 0;" ::: "memory")

__device__ __forceinline__ void ldsm4(uint32_t addr, uint32_t* r) {
    asm volatile("ldmatrix.sync.aligned.m8n8.x4.shared.b16 {%0,%1,%2,%3}, [%4];"
                 : "=r"(r[0]), "=r"(r[1]), "=r"(r[2]), "=r"(r[3]) : "r"(addr));
}
__device__ __forceinline__ void mma_bf16(float* c, const uint32_t* a,
                                         uint32_t b0, uint32_t b1) {
    asm volatile(
        "mma.sync.aligned.m16n8k16.row.col.f32.bf16.bf16.f32 "
        "{%0,%1,%2,%3}, {%4,%5,%6,%7}, {%8,%9}, {%0,%1,%2,%3};"
        : "+f"(c[0]), "+f"(c[1]), "+f"(c[2]), "+f"(c[3])
        : "r"(a[0]), "r"(a[1]), "r"(a[2]), "r"(a[3]), "r"(b0), "r"(b1));
}
__device__ __forceinline__ float wsum(float v) {
#pragma unroll
    for (int o = 16; o > 0; o >>= 1) v += __shfl_xor_sync(0xffffffffu, v, o);
    return v;
}

// ---------------------------------------------------------------------------
// Kernel A: hyperbolic transform -> tangent -> bf16 hi/lo, K-major transposed.
// Warp-per-row: lane owns output cols (lane, lane+32); all reductions shfl.
// ---------------------------------------------------------------------------
__global__ __launch_bounds__(256) void transform_kernel(
    const float* __restrict__ X,
    const float* __restrict__ W,
    const float* __restrict__ bias)
{
    __shared__ float2 sW2[DIN * 32];   // [k][t] = (W[k][t], W[k][t+32])

    const int tid = threadIdx.x;
    for (int i = tid; i < DIN * 32; i += 256) {
        const int k = i >> 5, t = i & 31;
        sW2[i] = make_float2(W[k * DOUT + t], W[k * DOUT + t + 32]);
    }
    __syncthreads();

    const int w    = tid >> 5;
    const int lane = tid & 31;
    const int row  = blockIdx.x * 8 + w;

    // hyp_bias = proj(expmap0(bias)) (warp-redundant, cheap)
    float b1 = bias[lane], b2v = bias[lane + 32];
    float b2 = wsum(b1 * b1 + b2v * b2v);
    float bn = fmaxf(sqrtf(b2), MIN_NORM);
    float tb = tanhf(bn) / bn;
    float e1 = tb * b1, e2v = tb * b2v;
    float e2 = wsum(e1 * e1 + e2v * e2v);
    float en = fmaxf(sqrtf(e2), MIN_NORM);
    float sc = (en > MAXNORM) ? (MAXNORM / en) : 1.f;
    float h1 = e1 * sc, h2v = e2v * sc;
    float h2 = wsum(h1 * h1 + h2v * h2v);

    // x (4 regs/lane), x2
    float xr[4];
#pragma unroll
    for (int j = 0; j < 4; ++j) xr[j] = X[(size_t)row * DIN + lane + 32 * j];
    float x2 = wsum(xr[0] * xr[0] + xr[1] * xr[1] + xr[2] * xr[2] + xr[3] * xr[3]);

    // mx = x @ W for cols lane, lane+32 (x broadcast via shfl)
    float ma = 0.f, mb = 0.f;
#pragma unroll
    for (int j = 0; j < 4; ++j) {
#pragma unroll
        for (int l = 0; l < 32; ++l) {
            const float xv = __shfl_sync(0xffffffffu, xr[j], l);
            const float2 wv = sW2[(j * 32 + l) * 32 + lane];
            ma = fmaf(xv, wv.x, ma);
            mb = fmaf(xv, wv.y, mb);
        }
    }

    float m2 = wsum(ma * ma + mb * mb);
    float xn = fmaxf(sqrtf(x2), MIN_NORM);
    float mn = fmaxf(sqrtf(m2), MIN_NORM);

    // mobius_matvec (sqrt_c = 1)
    float artx = atanhf(fminf(xn, ART_CLAMP));
    float tf   = tanhf(mn / xn * artx) / mn;
    float r1 = tf * ma, r2v = tf * mb;
    if (m2 == 0.f) { r1 = 0.f; r2v = 0.f; }

    // mobius_add(r, h)
    float r2 = wsum(r1 * r1 + r2v * r2v);
    float rh = wsum(r1 * h1 + r2v * h2v);
    float al  = 1.f + 2.f * rh + h2;
    float den = fmaxf(1.f + 2.f * rh + r2 * h2, MIN_NORM);
    float p1  = (al * r1  + (1.f - r2) * h1)  / den;
    float p2v = (al * r2v + (1.f - r2) * h2v) / den;

    // proj
    float p2 = wsum(p1 * p1 + p2v * p2v);
    float pn = fmaxf(sqrtf(p2), MIN_NORM);
    if (pn > MAXNORM) {
        float s = MAXNORM / pn;
        p1 *= s; p2v *= s; pn = MAXNORM;
    }

    // logmap0
    float lf = atanhf(fminf(pn, ART_CLAMP)) / pn;
    float t1 = lf * p1, t2 = lf * p2v;

    // split + transposed store
    __nv_bfloat16 h1b = __float2bfloat16(t1);
    __nv_bfloat16 h2b = __float2bfloat16(t2);
    g_Bhi[(size_t)lane * KDIM + row]        = h1b;
    g_Bhi[(size_t)(lane + 32) * KDIM + row] = h2b;
    g_Blo[(size_t)lane * KDIM + row]        = __float2bfloat16(t1 - __bfloat162float(h1b));
    g_Blo[(size_t)(lane + 32) * KDIM + row] = __float2bfloat16(t2 - __bfloat162float(h2b));
}

// ---------------------------------------------------------------------------
// Kernel B: out = relu(A @ T) via mma.sync bf16-split.
// 128 CTAs x 256 thr; warp m16 x n64; K-chunk 64.
// A: LDG -> regs -> cvt (full-chunk prefetch window). B: 3-stage cp.async.
// MMA schedule: ldsm-all-first, nt-major bursts, dual accumulator banks.
// ---------------------------------------------------------------------------
struct APre { float2 v[16]; };

__device__ __forceinline__ void ldA(APre& p, const float* pa0, const float* pa8, int kb) {
#pragma unroll
    for (int kf = 0; kf < 4; ++kf) {
        p.v[kf * 4 + 0] = *(const float2*)(pa0 + kb + kf * 16);
        p.v[kf * 4 + 1] = *(const float2*)(pa0 + kb + kf * 16 + 8);
        p.v[kf * 4 + 2] = *(const float2*)(pa8 + kb + kf * 16);
        p.v[kf * 4 + 3] = *(const float2*)(pa8 + kb + kf * 16 + 8);
    }
}

// mma fragment order: a0=(g,c0) a1=(g+8,c0) a2=(g,c0+8) a3=(g+8,c0+8)
__device__ __forceinline__ void cvtA(const APre& p, uint32_t* ah, uint32_t* al) {
    const int map[4] = {0, 2, 1, 3};
#pragma unroll
    for (int kf = 0; kf < 4; ++kf) {
#pragma unroll
        for (int j = 0; j < 4; ++j) {
            const float2 v = p.v[kf * 4 + map[j]];
            const uint32_t h = cvt_bf16x2(v.x, v.y);
            const float lx = v.x - __uint_as_float(h << 16);
            const float ly = v.y - __uint_as_float(h & 0xFFFF0000u);
            ah[kf * 4 + j] = h;
            al[kf * 4 + j] = cvt_bf16x2(lx, ly);
        }
    }
}

__global__ __launch_bounds__(256, 1) void gemm_kernel(
    const float* __restrict__ A,
    float* __restrict__ out)
{
    extern __shared__ __align__(128) char sB[];   // [stage][hi/lo][64 * BPITCH]

    const int tid  = threadIdx.x;
    const int w    = tid >> 5;
    const int lane = tid & 31;
    const int g    = lane >> 2;
    const int t4   = lane & 3;
    const int m0   = blockIdx.x * 128;

    const float* pa0 = A + (size_t)(m0 + w * 16 + g) * KDIM + 2 * t4;
    const float* pa8 = pa0 + (size_t)8 * KDIM;

    // B cp.async mapping: 4 x 16B per thread per stage
    const int n0 = tid >> 3, q0 = tid & 7;
    const int n1 = (tid + 256) >> 3, q1 = tid & 7;
    const uint32_t sb0 = smem_u32(sB);
    const uint32_t dOff0 = (uint32_t)(n0 * BPITCH + q0 * 16);
    const uint32_t dOff1 = (uint32_t)(n1 * BPITCH + q1 * 16);
    const __nv_bfloat16* srcH0 = &g_Bhi[(size_t)n0 * KDIM + q0 * 8];
    const __nv_bfloat16* srcH1 = &g_Bhi[(size_t)n1 * KDIM + q1 * 8];
    const __nv_bfloat16* srcL0 = &g_Blo[(size_t)n0 * KDIM + q0 * 8];
    const __nv_bfloat16* srcL1 = &g_Blo[(size_t)n1 * KDIM + q1 * 8];

    // ldmatrix lane offset
    const uint32_t lmOff = (uint32_t)((lane & 7) * BPITCH + (lane >> 3) * 16);

    float accA[8][4], accB[8][4];
#pragma unroll
    for (int i = 0; i < 8; ++i)
#pragma unroll
        for (int j = 0; j < 4; ++j) { accA[i][j] = 0.f; accB[i][j] = 0.f; }

    // prologue: B stages 0,1 ; A chunk 0
#pragma unroll
    for (int s = 0; s < 2; ++s) {
        const int kb = s * TK;
        const uint32_t db = sb0 + (uint32_t)(s * 2 * BTILE);
        cp_async16(db + dOff0,         srcH0 + kb);
        cp_async16(db + dOff1,         srcH1 + kb);
        cp_async16(db + BTILE + dOff0, srcL0 + kb);
        cp_async16(db + BTILE + dOff1, srcL1 + kb);
        CP_COMMIT();
    }

    APre pre;
    ldA(pre, pa0, pa8, 0);

    uint32_t ahF[16], alF[16];

    for (int i = 0; i < NCH; ++i) {
        const int s = i % BSTAGES;

        if (i < NCH - 1) { CP_WAIT1(); } else { CP_WAIT0(); }
        __syncthreads();

        // issue B stage i+2 (slot last read at chunk i-1; barrier above makes it safe)
        if (i + 2 < NCH) {
            const int kb = (i + 2) * TK;
            const uint32_t db = sb0 + (uint32_t)(((i + 2) % BSTAGES) * 2 * BTILE);
            cp_async16(db + dOff0,         srcH0 + kb);
            cp_async16(db + dOff1,         srcH1 + kb);
            cp_async16(db + BTILE + dOff0, srcL0 + kb);
            cp_async16(db + BTILE + dOff1, srcL1 + kb);
            CP_COMMIT();
        }

        // convert A chunk i, then start prefetching chunk i+1 (full-chunk window)
        cvtA(pre, ahF, alF);
        if (i + 1 < NCH) ldA(pre, pa0, pa8, (i + 1) * TK);

        const uint32_t bhBase = sb0 + (uint32_t)(s * 2 * BTILE) + lmOff;
        const uint32_t blBase = bhBase + BTILE;

#pragma unroll
        for (int p = 0; p < 2; ++p) {
            const uint32_t* ah0 = ahF + (2 * p) * 4;
            const uint32_t* ah1 = ahF + (2 * p + 1) * 4;
            const uint32_t* al0 = alF + (2 * p) * 4;
            const uint32_t* al1 = alF + (2 * p + 1) * 4;
            const uint32_t pOff = (uint32_t)(p * 64);

            uint32_t bf[8][4];
            // hi tile: load all, then nt-major bursts (no acc chained twice in a row)
#pragma unroll
            for (int nt = 0; nt < 8; ++nt)
                ldsm4(bhBase + (uint32_t)(nt * 8 * BPITCH) + pOff, bf[nt]);
#pragma unroll
            for (int nt = 0; nt < 8; ++nt) mma_bf16(accA[nt], ah0, bf[nt][0], bf[nt][1]);
#pragma unroll
            for (int nt = 0; nt < 8; ++nt) mma_bf16(accB[nt], al0, bf[nt][0], bf[nt][1]);
#pragma unroll
            for (int nt = 0; nt < 8; ++nt) mma_bf16(accA[nt], ah1, bf[nt][2], bf[nt][3]);
#pragma unroll
            for (int nt = 0; nt < 8; ++nt) mma_bf16(accB[nt], al1, bf[nt][2], bf[nt][3]);
            // lo tile
#pragma unroll
            for (int nt = 0; nt < 8; ++nt)
                ldsm4(blBase + (uint32_t)(nt * 8 * BPITCH) + pOff, bf[nt]);
#pragma unroll
            for (int nt = 0; nt < 8; ++nt) mma_bf16(accA[nt], ah0, bf[nt][0], bf[nt][1]);
#pragma unroll
            for (int nt = 0; nt < 8; ++nt) mma_bf16(accB[nt], ah1, bf[nt][2], bf[nt][3]);
        }
    }

    // epilogue: relu(accA+accB)
    const int rowTop = m0 + w * 16 + g;
#pragma unroll
    for (int nt = 0; nt < 8; ++nt) {
        const int col = nt * 8 + t4 * 2;
        float2 v0 = make_float2(fmaxf(accA[nt][0] + accB[nt][0], 0.f),
                                fmaxf(accA[nt][1] + accB[nt][1], 0.f));
        float2 v1 = make_float2(fmaxf(accA[nt][2] + accB[nt][2], 0.f),
                                fmaxf(accA[nt][3] + accB[nt][3], 0.f));
        *(float2*)(out + (size_t)rowTop * DOUT + col)       = v0;
        *(float2*)(out + (size_t)(rowTop + 8) * DOUT + col) = v1;
    }
}

// ---------------------------------------------------------------------------
extern "C" void kernel_launch(void* const* d_in, const int* in_sizes, int n_in,
                              void* d_out, int out_size)
{
    const float* adj  = (const float*)d_in[0];   // [16384, 16384]
    const float* x    = (const float*)d_in[1];   // [16384, 128]
    const float* w    = (const float*)d_in[2];   // [128, 64]
    const float* bias = (const float*)d_in[3];   // [64]
    float* out = (float*)d_out;                  // [16384, 64]

    cudaFuncSetAttribute(gemm_kernel, cudaFuncAttributeMaxDynamicSharedMemorySize, SMEM_B_BYTES);

    transform_kernel<<<N_ROWS / 8, 256>>>(x, w, bias);
    gemm_kernel<<<N_ROWS / 128, 256, SMEM_B_BYTES>>>(adj, out);
}